// round 14
// baseline (speedup 1.0000x reference)
#include <cuda_runtime.h>
#include <cstdint>

typedef unsigned long long u64;
typedef ulonglong2 u64x2;

// ---- packed f32x2 helpers --------------------------------------------------
__device__ __forceinline__ u64 pk2(float a, float b) {
    u64 r; asm("mov.b64 %0, {%1,%2};" : "=l"(r) : "f"(a), "f"(b)); return r;
}
__device__ __forceinline__ void up2(u64 v, float& a, float& b) {
    asm("mov.b64 {%0,%1}, %2;" : "=f"(a), "=f"(b) : "l"(v));
}
__device__ __forceinline__ u64 fma2(u64 a, u64 b, u64 c) {
    u64 d; asm("fma.rn.f32x2 %0, %1, %2, %3;" : "=l"(d) : "l"(a), "l"(b), "l"(c)); return d;
}
__device__ __forceinline__ u64 add2(u64 a, u64 b) {
    u64 d; asm("add.rn.f32x2 %0, %1, %2;" : "=l"(d) : "l"(a), "l"(b)); return d;
}

// ---- problem constants -----------------------------------------------------
constexpr int D      = 64;
constexpr int M      = 2048;
constexpr int K      = 8;
constexpr int NTOK   = 32768;       // B*S
constexpr int PAIRS  = 128;         // token pairs per CTA (tok p, tok p+128)
constexpr int TPC    = 256;         // tokens per CTA
constexpr int CT     = 256;         // codes per staged tile
constexpr int NTILES = M / CT;      // 8
constexpr int NT     = 256;         // threads per CTA (8 warps, 1 CTA/SM)
constexpr int NCTA   = NTOK / TPC;  // 128 <= 148 SMs: perfectly balanced wave

// ---- dynamic smem layout (bytes) -------------------------------------------
constexpr int OFF_RP  = 0;                         // u64   RP[D][PAIRS]   65536
constexpr int OFF_CP  = OFF_RP + D * PAIRS * 8;    // float CP[D][CT]      65536
constexpr int OFF_MNB = OFF_CP + D * CT * 4;       // float4 MNB[NT][8]    32768
constexpr int OFF_C2  = OFF_MNB + NT * 8 * 16;     // float C2[CT]          1024
constexpr int OFF_R2  = OFF_C2 + CT * 4;           // u64   R2s[PAIRS]      1024
constexpr int OFF_CHO = OFF_R2 + PAIRS * 8;        // int2  CHO[PAIRS]      1024
constexpr int SMEMB   = OFF_CHO + PAIRS * 8;       // 166912 -> 1 CTA/SM
constexpr int OFF_MN  = OFF_CP;                    // float4 MN[NT][8] aliases CP

// 256 threads; thread (a = t&7, cg = t>>3) runs TWO passes per tile over the
// R11-proven 8x8 block: pass A = pairs {8a..8a+7}, pass B = pairs
// {64+8a..64+8a+7}, codes {8cg..8cg+7}. Pass-A argmin state in registers,
// pass-B state in private smem scratch (MNB). Staging amortizes over 256
// tokens (-9% total work vs R11) and grid 128 <= 148 SMs gives a perfectly
// balanced single wave. Numerics bit-identical to all passing rounds
// (rel_err 0.0 x10): per-(token,code) ascending-d FMA chains (passes
// partition pairs, not dims); d2 = (r2 - 2*cross) + c2 with c2 = two
// ascending 32-dim half-chains summed; strict-< ascending per-thread argmin
// + lexicographic (d2, idx) cross-thread merge over ascending code blocks.

__device__ __forceinline__ void compute_block(
    const u64* __restrict__ RP, const float* __restrict__ CP,
    int pair_base, int cg, u64 acc[8][8])
{
    #pragma unroll
    for (int p = 0; p < 8; p++)
        #pragma unroll
        for (int c = 0; c < 8; c++) acc[p][c] = 0ull;

    #pragma unroll 2
    for (int d = 0; d < D; d++) {
        const u64* rp = RP + d * PAIRS + pair_base;
        u64x2 rA = *(const u64x2*)(rp + 0);
        u64x2 rB = *(const u64x2*)(rp + 2);
        u64x2 rC = *(const u64x2*)(rp + 4);
        u64x2 rD = *(const u64x2*)(rp + 6);
        const float4* cf = (const float4*)(CP + d*CT + cg*8);
        float4 cA = cf[0], cB = cf[1];
        u64 cc0 = pk2(cA.x, cA.x), cc1 = pk2(cA.y, cA.y);
        u64 cc2 = pk2(cA.z, cA.z), cc3 = pk2(cA.w, cA.w);
        u64 cc4 = pk2(cB.x, cB.x), cc5 = pk2(cB.y, cB.y);
        u64 cc6 = pk2(cB.z, cB.z), cc7 = pk2(cB.w, cB.w);
        u64 rr[8] = {rA.x, rA.y, rB.x, rB.y, rC.x, rC.y, rD.x, rD.y};
        #pragma unroll
        for (int p = 0; p < 8; p++) {
            acc[p][0] = fma2(rr[p], cc0, acc[p][0]);
            acc[p][1] = fma2(rr[p], cc1, acc[p][1]);
            acc[p][2] = fma2(rr[p], cc2, acc[p][2]);
            acc[p][3] = fma2(rr[p], cc3, acc[p][3]);
            acc[p][4] = fma2(rr[p], cc4, acc[p][4]);
            acc[p][5] = fma2(rr[p], cc5, acc[p][5]);
            acc[p][6] = fma2(rr[p], cc6, acc[p][6]);
            acc[p][7] = fma2(rr[p], cc7, acc[p][7]);
        }
    }
}

__global__ void __launch_bounds__(NT, 1)
rvq_kernel(const float* __restrict__ x, const float* __restrict__ cb,
           float* __restrict__ qout, float* __restrict__ idxout)
{
    extern __shared__ __align__(16) char sm[];
    u64*    RP  = (u64*)(sm + OFF_RP);
    float*  CP  = (float*)(sm + OFF_CP);
    float4* MNB = (float4*)(sm + OFF_MNB);
    float*  C2  = (float*)(sm + OFF_C2);
    u64*    R2s = (u64*)(sm + OFF_R2);
    int2*   CHO = (int2*)(sm + OFF_CHO);
    float4* MN  = (float4*)(sm + OFF_MN);

    const int t    = threadIdx.x;
    const int base = blockIdx.x * TPC;
    const int pq   = t & 127;       // pair for init/update/output roles
    const int qh   = t >> 7;        // dim half (0..1): 32 dims each
    const int tok0 = base + pq;
    const int tok1 = tok0 + PAIRS;
    const int a    = t & 7;         // pair stripe within pass: pairs 8a..8a+7
    const int cg   = t >> 3;        // code group (0..31), 8 codes each

    const u64 NEG1 = pk2(-1.0f, -1.0f);
    const u64 NEG2 = pk2(-2.0f, -2.0f);
    const float FMAX = 3.402823466e38f;

    // ---- init: pack x into RP (pair p = tokens p, p+128) ----
    {
        const float4* xa = (const float4*)(x + (size_t)tok0 * D) + qh * 8;
        const float4* xb = (const float4*)(x + (size_t)tok1 * D) + qh * 8;
        #pragma unroll
        for (int i = 0; i < 8; i++) {
            float4 va = xa[i], vb = xb[i];
            int d = qh * 32 + i * 4;
            RP[(d+0)*PAIRS + pq] = pk2(va.x, vb.x);
            RP[(d+1)*PAIRS + pq] = pk2(va.y, vb.y);
            RP[(d+2)*PAIRS + pq] = pk2(va.z, vb.z);
            RP[(d+3)*PAIRS + pq] = pk2(va.w, vb.w);
        }
    }
    __syncthreads();

    for (int k = 0; k < K; k++) {
        const float* cbk = cb + (size_t)k * M * D;

        // ---- r2 per pair: ascending-d packed FMA chain ----
        if (t < PAIRS) {
            u64 n2 = 0ull;
            #pragma unroll 8
            for (int d = 0; d < D; d++) { u64 v = RP[d*PAIRS + t]; n2 = fma2(v, v, n2); }
            R2s[t] = n2;
        }
        __syncthreads();   // R2s visible before r2v reads

        // pass-A argmin state (registers)
        float mloA[8], mhiA[8]; int iloA[8], ihiA[8];
        #pragma unroll
        for (int s = 0; s < 8; s++) {
            mloA[s] = FMAX; mhiA[s] = FMAX; iloA[s] = 0; ihiA[s] = 0;
        }
        // pass-B argmin state (private smem scratch; thread-local, no hazard)
        #pragma unroll
        for (int s = 0; s < 8; s++)
            MNB[t*8 + s] = make_float4(FMAX, __int_as_float(0), FMAX, __int_as_float(0));

        for (int tile = 0; tile < NTILES; tile++) {
            // ---- stage 256 codes, one per thread; c2 = two half-chains ----
            {
                const float4* s0 = (const float4*)(cbk + (size_t)(tile * CT + t) * D);
                float c2a = 0.0f, c2b = 0.0f;
                #pragma unroll
                for (int i = 0; i < 8; i++) {          // dims 0..31
                    float4 v = s0[i]; int d = 4*i;
                    CP[(d+0)*CT + t] = v.x; CP[(d+1)*CT + t] = v.y;
                    CP[(d+2)*CT + t] = v.z; CP[(d+3)*CT + t] = v.w;
                    c2a = fmaf(v.x,v.x,c2a); c2a = fmaf(v.y,v.y,c2a);
                    c2a = fmaf(v.z,v.z,c2a); c2a = fmaf(v.w,v.w,c2a);
                }
                #pragma unroll
                for (int i = 8; i < 16; i++) {         // dims 32..63
                    float4 v = s0[i]; int d = 4*i;
                    CP[(d+0)*CT + t] = v.x; CP[(d+1)*CT + t] = v.y;
                    CP[(d+2)*CT + t] = v.z; CP[(d+3)*CT + t] = v.w;
                    c2b = fmaf(v.x,v.x,c2b); c2b = fmaf(v.y,v.y,c2b);
                    c2b = fmaf(v.z,v.z,c2b); c2b = fmaf(v.w,v.w,c2b);
                }
                C2[t] = c2a + c2b;   // two-half c2 sum
            }
            __syncthreads();

            const int jb = tile * CT + cg * 8;
            float4 c2A4 = *(const float4*)(C2 + cg*8);
            float4 c2B4 = *(const float4*)(C2 + cg*8 + 4);
            u64 cd[8];
            cd[0] = pk2(c2A4.x, c2A4.x); cd[1] = pk2(c2A4.y, c2A4.y);
            cd[2] = pk2(c2A4.z, c2A4.z); cd[3] = pk2(c2A4.w, c2A4.w);
            cd[4] = pk2(c2B4.x, c2B4.x); cd[5] = pk2(c2B4.y, c2B4.y);
            cd[6] = pk2(c2B4.z, c2B4.z); cd[7] = pk2(c2B4.w, c2B4.w);

            // ========== pass A: pairs 8a..8a+7 ==========
            {
                u64 acc[8][8];
                compute_block(RP, CP, 8*a, cg, acc);
                u64 r2v[8];
                {
                    const u64x2* rs = (const u64x2*)(R2s + 8*a);
                    u64x2 q0 = rs[0], q1 = rs[1], q2 = rs[2], q3 = rs[3];
                    r2v[0] = q0.x; r2v[1] = q0.y; r2v[2] = q1.x; r2v[3] = q1.y;
                    r2v[4] = q2.x; r2v[5] = q2.y; r2v[6] = q3.x; r2v[7] = q3.y;
                }
                #pragma unroll
                for (int c = 0; c < 8; c++) {
                    #pragma unroll
                    for (int p = 0; p < 8; p++) {
                        float lo, hi;
                        up2(add2(fma2(acc[p][c], NEG2, r2v[p]), cd[c]), lo, hi);
                        if (lo < mloA[p]) { mloA[p] = lo; iloA[p] = jb + c; }
                        if (hi < mhiA[p]) { mhiA[p] = hi; ihiA[p] = jb + c; }
                    }
                }
            }

            // ========== pass B: pairs 64+8a..64+8a+7 ==========
            {
                u64 acc[8][8];
                compute_block(RP, CP, 64 + 8*a, cg, acc);
                u64 r2v[8];
                {
                    const u64x2* rs = (const u64x2*)(R2s + 64 + 8*a);
                    u64x2 q0 = rs[0], q1 = rs[1], q2 = rs[2], q3 = rs[3];
                    r2v[0] = q0.x; r2v[1] = q0.y; r2v[2] = q1.x; r2v[3] = q1.y;
                    r2v[4] = q2.x; r2v[5] = q2.y; r2v[6] = q3.x; r2v[7] = q3.y;
                }
                #pragma unroll
                for (int p = 0; p < 8; p++) {
                    float4 st = MNB[t*8 + p];
                    float ml = st.x, mh = st.z;
                    int   il = __float_as_int(st.y), ih = __float_as_int(st.w);
                    #pragma unroll
                    for (int c = 0; c < 8; c++) {
                        float lo, hi;
                        up2(add2(fma2(acc[p][c], NEG2, r2v[p]), cd[c]), lo, hi);
                        if (lo < ml) { ml = lo; il = jb + c; }
                        if (hi < mh) { mh = hi; ih = jb + c; }
                    }
                    MNB[t*8 + p] = make_float4(ml, __int_as_float(il),
                                               mh, __int_as_float(ih));
                }
            }
            __syncthreads();   // CP/C2 consumed; next tile restages
        }

        // ---- publish pass-A state (MN aliases CP; tiles done) ----
        #pragma unroll
        for (int s = 0; s < 8; s++)
            MN[t*8 + s] = make_float4(mloA[s], __int_as_float(iloA[s]),
                                      mhiA[s], __int_as_float(ihiA[s]));
        __syncthreads();

        // ---- cross-thread argmin merge ----
        if (t < PAIRS) {
            const int p = t;
            const float4* src = (p < 64) ? MN : MNB;
            const int lp  = p & 63;
            const int pa  = lp >> 3;     // stripe
            const int sl  = lp & 7;      // slot within stripe
            float g0 = FMAX, g1 = FMAX;
            int gi0 = 0, gi1 = 0;
            #pragma unroll
            for (int c = 0; c < 32; c++) {   // ascending cg = ascending code blocks
                float4 v = src[(c*8 + pa)*8 + sl];
                float va = v.x, vb = v.z;
                int ia = __float_as_int(v.y), ib = __float_as_int(v.w);
                if (va < g0 || (va == g0 && ia < gi0)) { g0 = va; gi0 = ia; }
                if (vb < g1 || (vb == g1 && ib < gi1)) { g1 = vb; gi1 = ib; }
            }
            CHO[p] = make_int2(gi0, gi1);
            if (idxout) {
                idxout[(size_t)k * NTOK + base + p]         = (float)gi0;
                idxout[(size_t)k * NTOK + base + PAIRS + p] = (float)gi1;
            }
        }
        __syncthreads();

        // ---- residual update: RP[d][p] -= code (exact fma(-1,c,r)) ----
        {
            int2 ch = CHO[pq];
            const float4* ca = (const float4*)(cbk + (size_t)ch.x * D) + qh * 8;
            const float4* cw = (const float4*)(cbk + (size_t)ch.y * D) + qh * 8;
            #pragma unroll
            for (int i = 0; i < 8; i++) {
                float4 u = ca[i], w = cw[i];
                int d = qh * 32 + i * 4;
                RP[(d+0)*PAIRS+pq] = fma2(pk2(u.x, w.x), NEG1, RP[(d+0)*PAIRS+pq]);
                RP[(d+1)*PAIRS+pq] = fma2(pk2(u.y, w.y), NEG1, RP[(d+1)*PAIRS+pq]);
                RP[(d+2)*PAIRS+pq] = fma2(pk2(u.z, w.z), NEG1, RP[(d+2)*PAIRS+pq]);
                RP[(d+3)*PAIRS+pq] = fma2(pk2(u.w, w.w), NEG1, RP[(d+3)*PAIRS+pq]);
            }
        }
        __syncthreads();
    }

    // ---- output: quantized = x - residual (exact elementwise) ----
    {
        const float4* xa = (const float4*)(x + (size_t)tok0 * D) + qh * 8;
        const float4* xb = (const float4*)(x + (size_t)tok1 * D) + qh * 8;
        float4* qa = (float4*)(qout + (size_t)tok0 * D) + qh * 8;
        float4* qb = (float4*)(qout + (size_t)tok1 * D) + qh * 8;
        #pragma unroll
        for (int i = 0; i < 8; i++) {
            float4 va = xa[i], vb = xb[i];
            float4 oa, ob; float lo, hi;
            int d = qh * 32 + i * 4;
            up2(RP[(d+0)*PAIRS+pq], lo, hi); oa.x = va.x - lo; ob.x = vb.x - hi;
            up2(RP[(d+1)*PAIRS+pq], lo, hi); oa.y = va.y - lo; ob.y = vb.y - hi;
            up2(RP[(d+2)*PAIRS+pq], lo, hi); oa.z = va.z - lo; ob.z = vb.z - hi;
            up2(RP[(d+3)*PAIRS+pq], lo, hi); oa.w = va.w - lo; ob.w = vb.w - hi;
            qa[i] = oa; qb[i] = ob;
        }
    }
}

extern "C" void kernel_launch(void* const* d_in, const int* in_sizes, int n_in,
                              void* d_out, int out_size)
{
    const float* x  = (const float*)d_in[0];
    const float* cb = (const float*)d_in[1];
    if (n_in >= 2 && in_sizes[0] == K * M * D && in_sizes[1] == NTOK * D) {
        x  = (const float*)d_in[1];
        cb = (const float*)d_in[0];
    }
    float* q = (float*)d_out;
    float* idxf = (out_size >= NTOK * D + K * NTOK) ? (q + (size_t)NTOK * D) : nullptr;

    cudaFuncSetAttribute(rvq_kernel, cudaFuncAttributeMaxDynamicSharedMemorySize, SMEMB);
    rvq_kernel<<<NCTA, NT, SMEMB>>>(x, cb, q, idxf);
}

// round 15
// speedup vs baseline: 1.4452x; 1.4452x over previous
#include <cuda_runtime.h>
#include <cstdint>

typedef unsigned long long u64;
typedef ulonglong2 u64x2;

// ---- packed f32x2 helpers --------------------------------------------------
__device__ __forceinline__ u64 pk2(float a, float b) {
    u64 r; asm("mov.b64 %0, {%1,%2};" : "=l"(r) : "f"(a), "f"(b)); return r;
}
__device__ __forceinline__ void up2(u64 v, float& a, float& b) {
    asm("mov.b64 {%0,%1}, %2;" : "=f"(a), "=f"(b) : "l"(v));
}
__device__ __forceinline__ u64 fma2(u64 a, u64 b, u64 c) {
    u64 d; asm("fma.rn.f32x2 %0, %1, %2, %3;" : "=l"(d) : "l"(a), "l"(b), "l"(c)); return d;
}
__device__ __forceinline__ u64 add2(u64 a, u64 b) {
    u64 d; asm("add.rn.f32x2 %0, %1, %2;" : "=l"(d) : "l"(a), "l"(b)); return d;
}

// ---- problem constants -----------------------------------------------------
constexpr int D      = 64;
constexpr int M      = 2048;
constexpr int K      = 8;
constexpr int NTOK   = 32768;       // B*S
constexpr int PAIRS  = 28;          // token pairs per CTA (tok p, tok p+28)
constexpr int TPC    = 56;          // tokens per CTA (592*56 = 33152 >= 32768)
constexpr int CT     = 128;         // codes per staged tile
constexpr int NTILES = M / CT;      // 16
constexpr int NT     = 64;          // threads per CTA (2 warps)
constexpr int NCTA   = 592;         // = 148 SMs x 4 CTAs: PERFECT single wave

// ---- dynamic smem layout (bytes) -------------------------------------------
constexpr int OFF_RP  = 0;                        // u64   RP[D][PAIRS]   14336
constexpr int OFF_CP  = OFF_RP + D * PAIRS * 8;   // float CP[D][CT]      32768
constexpr int OFF_C2  = OFF_CP + D * CT * 4;      // float C2[CT]           512
constexpr int OFF_R2  = OFF_C2 + CT * 4;          // u64   R2s[PAIRS]       256
constexpr int OFF_CHO = OFF_R2 + 256;             // int2  CHO[PAIRS]       256
constexpr int SMEMB   = OFF_CHO + 256;            // 48384 -> 4 CTAs/SM
constexpr int OFF_MN  = OFF_CP;                   // float4 MN[NT][7] aliases CP

// 64 threads; thread (a = t&3, cg = t>>2) owns pairs {7a..7a+6} x codes
// {8cg..8cg+7} -> 56 FMA2 accumulators (7x8 block). Token ids clamped to
// NTOK-1: duplicated tokens recompute bit-identically and write identical
// values (benign). Grid 592 = 148x4 -> perfectly balanced single wave.
// Numerics bit-identical to all passing rounds (rel_err 0.0 x11):
// ascending-d FMA chains for cross/r2; d2 = (r2 - 2*cross) + c2 with c2 =
// two ascending 32-dim half-chains summed; strict-< ascending per-thread
// argmin + lexicographic (d2, idx) cross-thread merge over ascending blocks.
__global__ void __launch_bounds__(NT, 4)
rvq_kernel(const float* __restrict__ x, const float* __restrict__ cb,
           float* __restrict__ qout, float* __restrict__ idxout)
{
    extern __shared__ __align__(16) char sm[];
    u64*    RP  = (u64*)(sm + OFF_RP);
    float*  CP  = (float*)(sm + OFF_CP);
    float*  C2  = (float*)(sm + OFF_C2);
    u64*    R2s = (u64*)(sm + OFF_R2);
    int2*   CHO = (int2*)(sm + OFF_CHO);
    float4* MN  = (float4*)(sm + OFF_MN);

    const int t    = threadIdx.x;
    const int base = blockIdx.x * TPC;
    const int pq   = t >> 1;        // pair for init/update/output (0..31; <28 active)
    const int qh   = t & 1;         // dim half (0..1): 32 dims each
    const bool pact = (pq < PAIRS);
    const int tok0 = pact ? min(base + pq, NTOK - 1) : 0;
    const int tok1 = pact ? min(base + PAIRS + pq, NTOK - 1) : 0;
    const int a    = t & 3;         // pair stripe: pairs 7a..7a+6
    const int cg   = t >> 2;        // code group (0..15), 8 codes each

    const u64 NEG1 = pk2(-1.0f, -1.0f);
    const u64 NEG2 = pk2(-2.0f, -2.0f);
    const float FMAX = 3.402823466e38f;

    // ---- init: pack x into RP (pair p = tokens p, p+28 clamped) ----
    if (pact) {
        const float4* xa = (const float4*)(x + (size_t)tok0 * D) + qh * 8;
        const float4* xb = (const float4*)(x + (size_t)tok1 * D) + qh * 8;
        #pragma unroll
        for (int i = 0; i < 8; i++) {
            float4 va = xa[i], vb = xb[i];
            int d = qh * 32 + i * 4;
            RP[(d+0)*PAIRS + pq] = pk2(va.x, vb.x);
            RP[(d+1)*PAIRS + pq] = pk2(va.y, vb.y);
            RP[(d+2)*PAIRS + pq] = pk2(va.z, vb.z);
            RP[(d+3)*PAIRS + pq] = pk2(va.w, vb.w);
        }
    }
    __syncthreads();

    for (int k = 0; k < K; k++) {
        const float* cbk = cb + (size_t)k * M * D;

        // ---- r2 per pair: ascending-d packed FMA chain ----
        if (t < PAIRS) {
            u64 n2 = 0ull;
            #pragma unroll 8
            for (int d = 0; d < D; d++) { u64 v = RP[d*PAIRS + t]; n2 = fma2(v, v, n2); }
            R2s[t] = n2;
        }
        __syncthreads();   // R2s visible before r2v reads

        u64 r2v[7];
        #pragma unroll
        for (int j = 0; j < 7; j++) r2v[j] = R2s[7*a + j];

        float mlo[7], mhi[7]; int ilo[7], ihi[7];
        #pragma unroll
        for (int s = 0; s < 7; s++) {
            mlo[s] = FMAX; mhi[s] = FMAX; ilo[s] = 0; ihi[s] = 0;
        }

        for (int tile = 0; tile < NTILES; tile++) {
            // ---- stage 128 codes (codes 2t, 2t+1); c2 = two half-chains ----
            {
                const int c0 = tile * CT + 2 * t;
                const float4* s0 = (const float4*)(cbk + (size_t)c0 * D);
                float c2a = 0.0f, c2b = 0.0f, c2c = 0.0f, c2d = 0.0f;
                #pragma unroll
                for (int i = 0; i < 8; i++) {          // code 2t, dims 0..31
                    float4 v = s0[i]; int d = 4*i;
                    CP[(d+0)*CT + 2*t] = v.x; CP[(d+1)*CT + 2*t] = v.y;
                    CP[(d+2)*CT + 2*t] = v.z; CP[(d+3)*CT + 2*t] = v.w;
                    c2a = fmaf(v.x,v.x,c2a); c2a = fmaf(v.y,v.y,c2a);
                    c2a = fmaf(v.z,v.z,c2a); c2a = fmaf(v.w,v.w,c2a);
                }
                #pragma unroll
                for (int i = 8; i < 16; i++) {         // code 2t, dims 32..63
                    float4 v = s0[i]; int d = 4*i;
                    CP[(d+0)*CT + 2*t] = v.x; CP[(d+1)*CT + 2*t] = v.y;
                    CP[(d+2)*CT + 2*t] = v.z; CP[(d+3)*CT + 2*t] = v.w;
                    c2b = fmaf(v.x,v.x,c2b); c2b = fmaf(v.y,v.y,c2b);
                    c2b = fmaf(v.z,v.z,c2b); c2b = fmaf(v.w,v.w,c2b);
                }
                const float4* s1 = s0 + 16;            // code 2t+1
                #pragma unroll
                for (int i = 0; i < 8; i++) {
                    float4 v = s1[i]; int d = 4*i;
                    CP[(d+0)*CT + 2*t+1] = v.x; CP[(d+1)*CT + 2*t+1] = v.y;
                    CP[(d+2)*CT + 2*t+1] = v.z; CP[(d+3)*CT + 2*t+1] = v.w;
                    c2c = fmaf(v.x,v.x,c2c); c2c = fmaf(v.y,v.y,c2c);
                    c2c = fmaf(v.z,v.z,c2c); c2c = fmaf(v.w,v.w,c2c);
                }
                #pragma unroll
                for (int i = 8; i < 16; i++) {
                    float4 v = s1[i]; int d = 4*i;
                    CP[(d+0)*CT + 2*t+1] = v.x; CP[(d+1)*CT + 2*t+1] = v.y;
                    CP[(d+2)*CT + 2*t+1] = v.z; CP[(d+3)*CT + 2*t+1] = v.w;
                    c2d = fmaf(v.x,v.x,c2d); c2d = fmaf(v.y,v.y,c2d);
                    c2d = fmaf(v.z,v.z,c2d); c2d = fmaf(v.w,v.w,c2d);
                }
                C2[2*t]   = c2a + c2b;
                C2[2*t+1] = c2c + c2d;
            }
            __syncthreads();

            // ---- cross: 7 pairs x 8 codes per thread, ascending-d chains ----
            u64 acc[7][8];
            #pragma unroll
            for (int p = 0; p < 7; p++)
                #pragma unroll
                for (int c = 0; c < 8; c++) acc[p][c] = 0ull;

            #pragma unroll 2
            for (int d = 0; d < D; d++) {
                const u64* rp = RP + d * PAIRS + 7*a;
                u64 rr[7];
                #pragma unroll
                for (int j = 0; j < 7; j++) rr[j] = rp[j];
                const float4* cf = (const float4*)(CP + d*CT + cg*8);
                float4 cA = cf[0], cB = cf[1];
                u64 cc0 = pk2(cA.x, cA.x), cc1 = pk2(cA.y, cA.y);
                u64 cc2 = pk2(cA.z, cA.z), cc3 = pk2(cA.w, cA.w);
                u64 cc4 = pk2(cB.x, cB.x), cc5 = pk2(cB.y, cB.y);
                u64 cc6 = pk2(cB.z, cB.z), cc7 = pk2(cB.w, cB.w);
                #pragma unroll
                for (int p = 0; p < 7; p++) {
                    acc[p][0] = fma2(rr[p], cc0, acc[p][0]);
                    acc[p][1] = fma2(rr[p], cc1, acc[p][1]);
                    acc[p][2] = fma2(rr[p], cc2, acc[p][2]);
                    acc[p][3] = fma2(rr[p], cc3, acc[p][3]);
                    acc[p][4] = fma2(rr[p], cc4, acc[p][4]);
                    acc[p][5] = fma2(rr[p], cc5, acc[p][5]);
                    acc[p][6] = fma2(rr[p], cc6, acc[p][6]);
                    acc[p][7] = fma2(rr[p], cc7, acc[p][7]);
                }
            }

            // ---- d2 + running argmin (ascending code order per pair) ----
            const int jb = tile * CT + cg * 8;
            #pragma unroll
            for (int c = 0; c < 8; c++) {
                float c2s = C2[cg*8 + c];
                u64 c2dup = pk2(c2s, c2s);
                #pragma unroll
                for (int p = 0; p < 7; p++) {
                    float lo, hi;
                    up2(add2(fma2(acc[p][c], NEG2, r2v[p]), c2dup), lo, hi);
                    if (lo < mlo[p]) { mlo[p] = lo; ilo[p] = jb + c; }
                    if (hi < mhi[p]) { mhi[p] = hi; ihi[p] = jb + c; }
                }
            }
            __syncthreads();   // CP/C2 consumed; safe to restage / alias MN
        }

        // ---- cross-thread argmin merge (MN aliases CP) ----
        #pragma unroll
        for (int s = 0; s < 7; s++)
            MN[t*7 + s] = make_float4(mlo[s], __int_as_float(ilo[s]),
                                      mhi[s], __int_as_float(ihi[s]));
        __syncthreads();

        if (t < PAIRS) {
            const int p  = t;
            const int pa = p / 7;       // stripe of pair p (0..3)
            const int sl = p % 7;       // slot within stripe
            float g0 = FMAX, g1 = FMAX;
            int gi0 = 0, gi1 = 0;
            #pragma unroll
            for (int c = 0; c < 16; c++) {   // ascending cg = ascending code blocks
                float4 v = MN[(c*4 + pa)*7 + sl];
                float va = v.x, vb = v.z;
                int ia = __float_as_int(v.y), ib = __float_as_int(v.w);
                if (va < g0 || (va == g0 && ia < gi0)) { g0 = va; gi0 = ia; }
                if (vb < g1 || (vb == g1 && ib < gi1)) { g1 = vb; gi1 = ib; }
            }
            CHO[p] = make_int2(gi0, gi1);
            if (idxout) {
                // clamped ids: duplicated tokens write identical values
                idxout[(size_t)k * NTOK + min(base + p, NTOK - 1)]         = (float)gi0;
                idxout[(size_t)k * NTOK + min(base + PAIRS + p, NTOK - 1)] = (float)gi1;
            }
        }
        __syncthreads();

        // ---- residual update: RP[d][p] -= code (exact fma(-1,c,r)) ----
        if (pact) {
            int2 ch = CHO[pq];
            const float4* ca = (const float4*)(cbk + (size_t)ch.x * D) + qh * 8;
            const float4* cw = (const float4*)(cbk + (size_t)ch.y * D) + qh * 8;
            #pragma unroll
            for (int i = 0; i < 8; i++) {
                float4 u = ca[i], w = cw[i];
                int d = qh * 32 + i * 4;
                RP[(d+0)*PAIRS+pq] = fma2(pk2(u.x, w.x), NEG1, RP[(d+0)*PAIRS+pq]);
                RP[(d+1)*PAIRS+pq] = fma2(pk2(u.y, w.y), NEG1, RP[(d+1)*PAIRS+pq]);
                RP[(d+2)*PAIRS+pq] = fma2(pk2(u.z, w.z), NEG1, RP[(d+2)*PAIRS+pq]);
                RP[(d+3)*PAIRS+pq] = fma2(pk2(u.w, w.w), NEG1, RP[(d+3)*PAIRS+pq]);
            }
        }
        __syncthreads();
    }

    // ---- output: quantized = x - residual (exact elementwise) ----
    if (pact) {
        const float4* xa = (const float4*)(x + (size_t)tok0 * D) + qh * 8;
        const float4* xb = (const float4*)(x + (size_t)tok1 * D) + qh * 8;
        float4* qa = (float4*)(qout + (size_t)tok0 * D) + qh * 8;
        float4* qb = (float4*)(qout + (size_t)tok1 * D) + qh * 8;
        #pragma unroll
        for (int i = 0; i < 8; i++) {
            float4 va = xa[i], vb = xb[i];
            float4 oa, ob; float lo, hi;
            int d = qh * 32 + i * 4;
            up2(RP[(d+0)*PAIRS+pq], lo, hi); oa.x = va.x - lo; ob.x = vb.x - hi;
            up2(RP[(d+1)*PAIRS+pq], lo, hi); oa.y = va.y - lo; ob.y = vb.y - hi;
            up2(RP[(d+2)*PAIRS+pq], lo, hi); oa.z = va.z - lo; ob.z = vb.z - hi;
            up2(RP[(d+3)*PAIRS+pq], lo, hi); oa.w = va.w - lo; ob.w = vb.w - hi;
            qa[i] = oa; qb[i] = ob;
        }
    }
}

extern "C" void kernel_launch(void* const* d_in, const int* in_sizes, int n_in,
                              void* d_out, int out_size)
{
    const float* x  = (const float*)d_in[0];
    const float* cb = (const float*)d_in[1];
    if (n_in >= 2 && in_sizes[0] == K * M * D && in_sizes[1] == NTOK * D) {
        x  = (const float*)d_in[1];
        cb = (const float*)d_in[0];
    }
    float* q = (float*)d_out;
    float* idxf = (out_size >= NTOK * D + K * NTOK) ? (q + (size_t)NTOK * D) : nullptr;

    cudaFuncSetAttribute(rvq_kernel, cudaFuncAttributeMaxDynamicSharedMemorySize, SMEMB);
    rvq_kernel<<<NCTA, NT, SMEMB>>>(x, cb, q, idxf);
}